// round 1
// baseline (speedup 1.0000x reference)
#include <cuda_runtime.h>
#include <math.h>

#define NB 2
#define CH 256
#define G 1600
#define GW 40
#define L 6400
#define TOPK 8
#define K4 32

#define OFF_H01 0
#define OFF_H10 (NB*L*K4)              /* 409600 */
#define OFF_SC  (OFF_H10 + NB*L*K4)    /* 819200 */
#define OFF_JB  (OFF_SC + NB*L)        /* 832000 */
#define OFF_MK  (OFF_JB + NB*L)        /* 844800 */
#define OFF_X0  (OFF_MK + NB*L)        /* 857600 */
#define OFF_X1  (OFF_X0 + NB*CH*L)     /* 4134400 */

// ---------------- scratch (static device globals; no runtime allocs) ----------------
__device__ float g_sim[NB*G*G];          // 20.5 MB
__device__ int   g_i01[NB*G*TOPK];
__device__ int   g_i10[NB*G*TOPK];
__device__ int   g_ind0[NB*L*K4];        // (n, l0, k)
__device__ int   g_ind1[NB*L*K4];        // (n, l1, k)   (pre-swap layout)
__device__ float g_h01p[NB*L*K4];        // ungated h01, (n, l0, k)
__device__ float g_h10p[NB*L*K4];        // ungated h10, (n, l1, k)
__device__ float g_score[NB*L];
__device__ int   g_jb[NB*L];
__device__ int   g_ib[NB*L];

// ---------------- K1: sim = p0^T p1 (scale dropped: only feeds top-k) ----------------
__global__ void k_gemm(const float* __restrict__ p0, const float* __restrict__ p1) {
    const int n = blockIdx.z;
    const float* A = p0 + (long)n*CH*G;   // (c, i): row-major over i
    const float* B = p1 + (long)n*CH*G;
    float* S = g_sim + (long)n*G*G;
    __shared__ float As[16][128];
    __shared__ float Bs[16][128];
    const int tid = threadIdx.x;
    const int tx = tid & 15, ty = tid >> 4;
    const int i0 = blockIdx.y * 128, j0 = blockIdx.x * 128;
    float acc[8][8];
#pragma unroll
    for (int a = 0; a < 8; a++)
#pragma unroll
        for (int b = 0; b < 8; b++) acc[a][b] = 0.f;

    for (int k0 = 0; k0 < CH; k0 += 16) {
#pragma unroll
        for (int r = 0; r < 2; r++) {
            int idx = tid + r*256;          // 512 float4 loads per operand tile
            int kk  = idx >> 5;
            int ii  = (idx & 31) << 2;
            float4 va = make_float4(0.f,0.f,0.f,0.f);
            float4 vb = va;
            long rowo = (long)(k0 + kk) * G;
            int gi = i0 + ii, gj = j0 + ii;
            if (gi < G) va = *(const float4*)(A + rowo + gi);
            if (gj < G) vb = *(const float4*)(B + rowo + gj);
            *(float4*)&As[kk][ii] = va;
            *(float4*)&Bs[kk][ii] = vb;
        }
        __syncthreads();
#pragma unroll
        for (int kk = 0; kk < 16; kk++) {
            float ra[8], rb[8];
#pragma unroll
            for (int a = 0; a < 8; a++) ra[a] = As[kk][ty*8 + a];
#pragma unroll
            for (int b = 0; b < 8; b++) rb[b] = Bs[kk][tx*8 + b];
#pragma unroll
            for (int a = 0; a < 8; a++)
#pragma unroll
                for (int b = 0; b < 8; b++) acc[a][b] += ra[a]*rb[b];
        }
        __syncthreads();
    }
#pragma unroll
    for (int a = 0; a < 8; a++) {
        int i = i0 + ty*8 + a;
        if (i < G) {
#pragma unroll
            for (int b = 0; b < 8; b++) {
                int j = j0 + tx*8 + b;
                if (j < G) S[(long)i*G + j] = acc[a][b];
            }
        }
    }
}

// ---------------- K2: top-8 per row (mode 0) and per column (mode 1) ----------------
// jax.lax.top_k semantics: descending value, ties -> smaller index first.
__global__ void k_topk() {
    __shared__ float vals[G];
    __shared__ float rv[256];
    __shared__ int   ri[256];
    int row = blockIdx.x, n = blockIdx.y, mode = blockIdx.z;
    const float* S = g_sim + (long)n*G*G;
    for (int i = threadIdx.x; i < G; i += 256)
        vals[i] = (mode == 0) ? S[(long)row*G + i] : S[(long)i*G + row];
    __syncthreads();
    int* outp = (mode == 0 ? g_i01 : g_i10) + (n*G + row)*TOPK;
    for (int r = 0; r < TOPK; r++) {
        float best = -INFINITY; int bi = G;
        for (int i = threadIdx.x; i < G; i += 256) {
            float v = vals[i];
            if (v > best || (v == best && i < bi)) { best = v; bi = i; }
        }
        rv[threadIdx.x] = best; ri[threadIdx.x] = bi;
        __syncthreads();
        for (int s = 128; s > 0; s >>= 1) {
            if (threadIdx.x < s) {
                float v2 = rv[threadIdx.x + s]; int i2 = ri[threadIdx.x + s];
                if (v2 > rv[threadIdx.x] ||
                    (v2 == rv[threadIdx.x] && i2 < ri[threadIdx.x])) {
                    rv[threadIdx.x] = v2; ri[threadIdx.x] = i2;
                }
            }
            __syncthreads();
        }
        if (threadIdx.x == 0) { outp[r] = ri[0]; vals[ri[0]] = -INFINITY; }
        __syncthreads();
    }
}

// ---------------- K3: fine-index tables ----------------
__global__ void k_ind() {
    int idx = blockIdx.x*blockDim.x + threadIdx.x;
    if (idx >= NB*L*K4) return;
    int k = idx & 31;
    int l = (idx >> 5) % L;
    int n = idx / (L*K4);
    int r = l / 80, c = l % 80;
    int g = (r >> 1)*GW + (c >> 1);
    int t = k >> 2, e = k & 3;
    int ey = e >> 1, ex = e & 1;
    int c01 = g_i01[(n*G + g)*TOPK + t];
    g_ind0[idx] = ((c01/GW)*2 + ey)*80 + (c01%GW)*2 + ex;
    int c10 = g_i10[(n*G + g)*TOPK + t];
    g_ind1[idx] = ((c10/GW)*2 + ey)*80 + (c10%GW)*2 + ex;
}

// ---------------- K4: s = x·aᵀ/(C·TEMP), softmax over k, permuted store ----------------
__global__ void k_heat(const float* __restrict__ x0, const float* __restrict__ x1,
                       const float* __restrict__ a01, const float* __restrict__ a10) {
    __shared__ float as[CH*33];     // a transposed [c][k], pad 33 -> conflict-free
    __shared__ float xs[CH*5];      // x [c][q], pad 5
    __shared__ float red[4*4*32];
    int g = blockIdx.x, n = blockIdx.y, dir = blockIdx.z;
    const float* X = (dir == 0 ? x0  : x1 ) + (long)(n*G + g)*4*CH;
    const float* A = (dir == 0 ? a01 : a10) + (long)(n*G + g)*K4*CH;
    float* OUT = (dir == 0 ? g_h01p : g_h10p) + (long)n*L*K4;
    int tid = threadIdx.x;

    for (int idx4 = tid; idx4 < K4*CH/4; idx4 += 128) {
        int k = idx4 >> 6;
        int c = (idx4 & 63) << 2;
        float4 v = *(const float4*)(A + (long)k*CH + c);
        as[(c+0)*33+k] = v.x; as[(c+1)*33+k] = v.y;
        as[(c+2)*33+k] = v.z; as[(c+3)*33+k] = v.w;
    }
    for (int idx4 = tid; idx4 < 4*CH/4; idx4 += 128) {
        int q = idx4 >> 6;
        int c = (idx4 & 63) << 2;
        float4 v = *(const float4*)(X + (long)q*CH + c);
        xs[(c+0)*5+q] = v.x; xs[(c+1)*5+q] = v.y;
        xs[(c+2)*5+q] = v.z; xs[(c+3)*5+q] = v.w;
    }
    __syncthreads();

    int k = tid & 31, w = tid >> 5;
    float acc0 = 0.f, acc1 = 0.f, acc2 = 0.f, acc3 = 0.f;
#pragma unroll 4
    for (int c = w*64; c < w*64 + 64; c++) {
        float a = as[c*33 + k];
        acc0 += a * xs[c*5 + 0];
        acc1 += a * xs[c*5 + 1];
        acc2 += a * xs[c*5 + 2];
        acc3 += a * xs[c*5 + 3];
    }
    red[(w*4+0)*32+k] = acc0; red[(w*4+1)*32+k] = acc1;
    red[(w*4+2)*32+k] = acc2; red[(w*4+3)*32+k] = acc3;
    __syncthreads();

    int q = w;
    float s = red[(0*4+q)*32+k] + red[(1*4+q)*32+k]
            + red[(2*4+q)*32+k] + red[(3*4+q)*32+k];
    float logit = s * (1.f/25.6f);   // /C /TEMP
    float m = logit;
#pragma unroll
    for (int o = 16; o > 0; o >>= 1) m = fmaxf(m, __shfl_xor_sync(~0u, m, o));
    float p = expf(logit - m);
    float sum = p;
#pragma unroll
    for (int o = 16; o > 0; o >>= 1) sum += __shfl_xor_sync(~0u, sum, o);
    float h = p / sum;
    int gh = g / GW, gw = g % GW, qr = q >> 1, qc = q & 1;
    int l = (gh*2 + qr)*80 + gw*2 + qc;
    OUT[(long)l*K4 + k] = h;
}

// ---------------- K5: mutual gating (dense scatter reduced to 8-way i10/i01 search) --
__global__ void k_gate01(float* __restrict__ out) {
    int idx = blockIdx.x*blockDim.x + threadIdx.x;    // (n, l0, k)
    if (idx >= NB*L*K4) return;
    int n  = idx / (L*K4);
    int l0 = (idx >> 5) % L;
    int j  = g_ind0[idx];
    int r0 = l0/80, c0 = l0%80;
    int e  = ((r0 & 1) << 1) | (c0 & 1);
    int gl = (r0 >> 1)*GW + (c0 >> 1);
    int gj = ((j/80) >> 1)*GW + ((j%80) >> 1);
    const int* i10p = g_i10 + (n*G + gj)*TOPK;
    float f = 0.f;
#pragma unroll
    for (int t = 0; t < TOPK; t++)
        if (i10p[t] == gl) { f = g_h10p[((long)n*L + j)*K4 + t*4 + e]; break; }
    out[idx] = g_h01p[idx] * f;
}

__global__ void k_gate10(float* __restrict__ out) {
    int idx = blockIdx.x*blockDim.x + threadIdx.x;    // (n, k, l1), l1 innermost
    if (idx >= NB*L*K4) return;
    int l1 = idx % L;
    int k  = (idx / L) % K4;
    int n  = idx / (L*K4);
    int l0 = g_ind1[((long)n*L + l1)*K4 + k];
    int r1 = l1/80, c1 = l1%80;
    int e  = ((r1 & 1) << 1) | (c1 & 1);
    int gl1 = (r1 >> 1)*GW + (c1 >> 1);
    int gl0 = ((l0/80) >> 1)*GW + ((l0%80) >> 1);
    const int* i01p = g_i01 + (n*G + gl0)*TOPK;
    float f = 0.f;
#pragma unroll
    for (int t = 0; t < TOPK; t++)
        if (i01p[t] == gl1) { f = g_h01p[((long)n*L + l0)*K4 + t*4 + e]; break; }
    out[idx] = g_h10p[((long)n*L + l1)*K4 + k] * f;
}

// ---------------- K6: coarse matching ----------------
__global__ void k_matchA(const float* __restrict__ h01) {
    int idx = blockIdx.x*blockDim.x + threadIdx.x;
    if (idx >= NB*L) return;
    int l0 = idx % L;
    const float* row = h01 + (long)idx*K4;
    float best = -1.f; int bk = 0;
#pragma unroll
    for (int k = 0; k < K4; k++) { float v = row[k]; if (v > best) { best = v; bk = k; } }
    g_score[idx] = best;
    int jb = g_ind0[(long)idx*K4 + bk];
    int r = l0/80, c = l0%80;
    if (r < 2 || r >= 78 || c < 2 || c >= 78) jb = 0;
    g_jb[idx] = jb;
}

__global__ void k_matchB(const float* __restrict__ h10) {
    int idx = blockIdx.x*blockDim.x + threadIdx.x;
    if (idx >= NB*L) return;
    int n = idx / L, l1 = idx % L;
    float best = -1.f; int bk = 0;
#pragma unroll
    for (int k = 0; k < K4; k++) {
        float v = h10[((long)n*K4 + k)*L + l1];
        if (v > best) { best = v; bk = k; }
    }
    int ib = g_ind1[((long)n*L + l1)*K4 + bk];
    int r = l1/80, c = l1%80;
    if (r < 2 || r >= 78 || c < 2 || c >= 78) ib = 0;
    g_ib[idx] = ib;
}

__global__ void k_matchC(float* __restrict__ osc, float* __restrict__ ojb,
                         float* __restrict__ omk) {
    int idx = blockIdx.x*blockDim.x + threadIdx.x;
    if (idx >= NB*L) return;
    int n = idx / L, l0 = idx % L;
    int jb = g_jb[idx];
    int biproj = g_ib[n*L + jb];
    float sc = g_score[idx];
    bool m = (biproj == l0) && (l0 != 0) && (sc > 0.2f);
    omk[idx] = m ? 1.f : 0.f;
    osc[idx] = m ? sc : 0.f;
    ojb[idx] = (float)jb;
}

// ---------------- K7: unpatchify via padded SMEM tile (both sides coalesced) --------
__global__ void k_unpatch(const float* __restrict__ x0, const float* __restrict__ x1,
                          float* __restrict__ out) {
    __shared__ float s[160*17];
    int c0 = blockIdx.x * 16;
    int gh = blockIdx.y;
    int which = blockIdx.z >> 1, n = blockIdx.z & 1;
    const float* X = (which == 0 ? x0 : x1) + (long)(n*G + gh*GW)*4*CH;
    float* O = out + (which == 0 ? OFF_X0 : OFF_X1);
    for (int idx = threadIdx.x; idx < 2560; idx += 256) {
        int gq = idx >> 4, cc = idx & 15;        // gq = g'*4 + q
        s[gq*17 + cc] = X[(long)gq*CH + c0 + cc];
    }
    __syncthreads();
    for (int idx = threadIdx.x; idx < 2560; idx += 256) {
        int w  = idx % 80;
        int t2 = idx / 80;
        int qr = t2 & 1, cc = t2 >> 1;
        int gp = w >> 1, qc = w & 1;
        float v = s[(gp*4 + qr*2 + qc)*17 + cc];
        O[(((long)(n*CH + c0 + cc))*80 + gh*2 + qr)*80 + w] = v;
    }
}

// ---------------- launch ----------------
extern "C" void kernel_launch(void* const* d_in, const int* in_sizes, int n_in,
                              void* d_out, int out_size) {
    const float* x0  = (const float*)d_in[0];
    const float* x1  = (const float*)d_in[1];
    const float* a01 = (const float*)d_in[2];
    const float* a10 = (const float*)d_in[3];
    const float* p0  = (const float*)d_in[4];
    const float* p1  = (const float*)d_in[5];
    float* out = (float*)d_out;

    k_gemm <<<dim3(13,13,2), 256>>>(p0, p1);
    k_topk <<<dim3(G,2,2),   256>>>();
    k_ind  <<<(NB*L*K4 + 255)/256, 256>>>();
    k_heat <<<dim3(G,2,2),   128>>>(x0, x1, a01, a10);
    k_gate01<<<(NB*L*K4 + 255)/256, 256>>>(out + OFF_H01);
    k_gate10<<<(NB*L*K4 + 255)/256, 256>>>(out + OFF_H10);
    k_matchA<<<(NB*L + 255)/256, 256>>>(out + OFF_H01);
    k_matchB<<<(NB*L + 255)/256, 256>>>(out + OFF_H10);
    k_matchC<<<(NB*L + 255)/256, 256>>>(out + OFF_SC, out + OFF_JB, out + OFF_MK);
    k_unpatch<<<dim3(16,40,4), 256>>>(x0, x1, out);
}

// round 2
// speedup vs baseline: 1.3272x; 1.3272x over previous
#include <cuda_runtime.h>
#include <math.h>

#define NB 2
#define CH 256
#define G 1600
#define GW 40
#define L 6400
#define TOPK 8
#define K4 32

#define OFF_H01 0
#define OFF_H10 (NB*L*K4)              /* 409600 */
#define OFF_SC  (OFF_H10 + NB*L*K4)    /* 819200 */
#define OFF_JB  (OFF_SC + NB*L)        /* 832000 */
#define OFF_MK  (OFF_JB + NB*L)        /* 844800 */
#define OFF_X0  (OFF_MK + NB*L)        /* 857600 */
#define OFF_X1  (OFF_X0 + NB*CH*L)     /* 4134400 */

// ---------------- scratch (static device globals; no runtime allocs) ----------------
__device__ float g_sim [NB*G*G];         // 20.5 MB
__device__ float g_simT[NB*G*G];         // 20.5 MB (transposed, for column top-k)
__device__ int   g_i01[NB*G*TOPK];
__device__ int   g_i10[NB*G*TOPK];
__device__ int   g_ind0[NB*L*K4];        // (n, l0, k)
__device__ int   g_ind1[NB*L*K4];        // (n, l1, k)   (pre-swap layout)
__device__ float g_h01p[NB*L*K4];        // ungated h01, (n, l0, k)
__device__ float g_h10p[NB*L*K4];        // ungated h10, (n, l1, k)
__device__ float g_score[NB*L];
__device__ int   g_jb[NB*L];
__device__ int   g_ib[NB*L];

// ---------------- K1: sim = p0^T p1 (scale dropped: only feeds top-k) ----------------
// 64 (rows, exact) x 128 (cols) tile, 256 threads, 4x8 per thread, LDS.128 operands.
__global__ void k_gemm(const float* __restrict__ p0, const float* __restrict__ p1) {
    const int n = blockIdx.z;
    const float* A = p0 + (long)n*CH*G;   // (c, i)
    const float* B = p1 + (long)n*CH*G;
    float* S = g_sim + (long)n*G*G;
    __shared__ float As[16][64];
    __shared__ float Bs[16][128];
    const int tid = threadIdx.x;
    const int tx = tid & 15, ty = tid >> 4;
    const int i0 = blockIdx.y * 64;    // 25 blocks, exact
    const int j0 = blockIdx.x * 128;   // 13 blocks, bounded
    float acc[4][8];
#pragma unroll
    for (int a = 0; a < 4; a++)
#pragma unroll
        for (int b = 0; b < 8; b++) acc[a][b] = 0.f;

    for (int k0 = 0; k0 < CH; k0 += 16) {
        {   // A tile: 16x64 = 256 float4, one per thread (rows always in-bounds)
            int kk = tid >> 4, ii = (tid & 15) << 2;
            *(float4*)&As[kk][ii] = *(const float4*)(A + (long)(k0 + kk)*G + i0 + ii);
        }
#pragma unroll
        for (int r = 0; r < 2; r++) {   // B tile: 16x128 = 512 float4
            int idx = tid + r*256;
            int kk = idx >> 5, jj = (idx & 31) << 2;
            int gj = j0 + jj;
            float4 v = make_float4(0.f,0.f,0.f,0.f);
            if (gj < G) v = *(const float4*)(B + (long)(k0 + kk)*G + gj);
            *(float4*)&Bs[kk][jj] = v;
        }
        __syncthreads();
#pragma unroll
        for (int kk = 0; kk < 16; kk++) {
            float4 ra  = *(const float4*)&As[kk][ty*4];
            float4 rb0 = *(const float4*)&Bs[kk][tx*8];
            float4 rb1 = *(const float4*)&Bs[kk][tx*8 + 4];
            float ar[4] = {ra.x, ra.y, ra.z, ra.w};
            float br[8] = {rb0.x, rb0.y, rb0.z, rb0.w, rb1.x, rb1.y, rb1.z, rb1.w};
#pragma unroll
            for (int a = 0; a < 4; a++)
#pragma unroll
                for (int b = 0; b < 8; b++) acc[a][b] += ar[a]*br[b];
        }
        __syncthreads();
    }
#pragma unroll
    for (int a = 0; a < 4; a++) {
        int i = i0 + ty*4 + a;
#pragma unroll
        for (int b4 = 0; b4 < 2; b4++) {
            int j = j0 + tx*8 + b4*4;
            if (j < G) {
                float4 v = make_float4(acc[a][b4*4], acc[a][b4*4+1],
                                       acc[a][b4*4+2], acc[a][b4*4+3]);
                *(float4*)(S + (long)i*G + j) = v;
            }
        }
    }
}

// ---------------- K1b: transpose sim (coalesced both sides) ----------------
__global__ void k_tr() {
    __shared__ float t[32][33];
    int n = blockIdx.z;
    int i0 = blockIdx.y * 32, j0 = blockIdx.x * 32;
    const float* S = g_sim  + (long)n*G*G;
    float*       T = g_simT + (long)n*G*G;
    int x = threadIdx.x, y = threadIdx.y;
#pragma unroll
    for (int dy = 0; dy < 32; dy += 8)
        t[y + dy][x] = S[(long)(i0 + y + dy)*G + j0 + x];
    __syncthreads();
#pragma unroll
    for (int dy = 0; dy < 32; dy += 8)
        T[(long)(j0 + y + dy)*G + i0 + x] = t[x][y + dy];
}

// ---------------- K2: top-8, warp-per-row, values in registers ----------------
// jax.lax.top_k semantics: descending value, ties -> smaller index first.
__global__ void k_topk() {
    int w = threadIdx.x >> 5, l = threadIdx.x & 31;
    int row = blockIdx.x * 8 + w;
    int n = blockIdx.y, mode = blockIdx.z;
    const float* Srow = (mode == 0 ? g_sim : g_simT) + (long)n*G*G + (long)row*G;
    float v[50];
#pragma unroll
    for (int j = 0; j < 50; j++) v[j] = Srow[j*32 + l];
    int* outp = (mode == 0 ? g_i01 : g_i10) + (n*G + row)*TOPK;
#pragma unroll
    for (int r = 0; r < TOPK; r++) {
        float best = -INFINITY; int bi = 1 << 30;
#pragma unroll
        for (int j = 0; j < 50; j++) {
            float val = v[j];
            int i = j*32 + l;
            if (val > best || (val == best && i < bi)) { best = val; bi = i; }
        }
#pragma unroll
        for (int o = 16; o > 0; o >>= 1) {
            float ov = __shfl_xor_sync(~0u, best, o);
            int   oi = __shfl_xor_sync(~0u, bi, o);
            if (ov > best || (ov == best && oi < bi)) { best = ov; bi = oi; }
        }
        if (l == 0) outp[r] = bi;
        if ((bi & 31) == l) {
            int jw = bi >> 5;
#pragma unroll
            for (int j = 0; j < 50; j++) if (j == jw) v[j] = -INFINITY;
        }
    }
}

// ---------------- K3: fine-index tables ----------------
__global__ void k_ind() {
    int idx = blockIdx.x*blockDim.x + threadIdx.x;
    if (idx >= NB*L*K4) return;
    int k = idx & 31;
    int l = (idx >> 5) % L;
    int n = idx / (L*K4);
    int r = l / 80, c = l % 80;
    int g = (r >> 1)*GW + (c >> 1);
    int t = k >> 2, e = k & 3;
    int ey = e >> 1, ex = e & 1;
    int c01 = g_i01[(n*G + g)*TOPK + t];
    g_ind0[idx] = ((c01/GW)*2 + ey)*80 + (c01%GW)*2 + ex;
    int c10 = g_i10[(n*G + g)*TOPK + t];
    g_ind1[idx] = ((c10/GW)*2 + ey)*80 + (c10%GW)*2 + ex;
}

// ---------------- K4: heatmaps — warp-cooperative dots, stream A from global -------
// 256 threads per (g, n, dir). Warp w handles k-rows [4w, 4w+4); X tile in smem
// read via conflict-free LDS.128; A streamed coalesced float4 from global.
__global__ void k_heat(const float* __restrict__ x0, const float* __restrict__ x1,
                       const float* __restrict__ a01, const float* __restrict__ a10) {
    __shared__ float xs[4*CH];        // 4 KB
    __shared__ float sred[4*32];
    int g = blockIdx.x, n = blockIdx.y, dir = blockIdx.z;
    const float* X = (dir == 0 ? x0  : x1 ) + (long)(n*G + g)*4*CH;
    const float* A = (dir == 0 ? a01 : a10) + (long)(n*G + g)*K4*CH;
    float* OUT = (dir == 0 ? g_h01p : g_h10p) + (long)n*L*K4;
    int tid = threadIdx.x;

    ((float4*)xs)[tid] = ((const float4*)X)[tid];   // 4*256 floats = 256 float4
    __syncthreads();

    int w = tid >> 5, l = tid & 31;
    const float4* A4 = (const float4*)A + (long)(w*4)*64;   // 4 rows x 64 float4
    float acc[4][4];
#pragma unroll
    for (int s = 0; s < 4; s++)
#pragma unroll
        for (int q = 0; q < 4; q++) acc[s][q] = 0.f;

#pragma unroll
    for (int it = 0; it < 2; it++) {
        float4 xv[4];
#pragma unroll
        for (int q = 0; q < 4; q++) xv[q] = ((const float4*)xs)[q*64 + it*32 + l];
#pragma unroll
        for (int s = 0; s < 4; s++) {
            float4 av = A4[s*64 + it*32 + l];
#pragma unroll
            for (int q = 0; q < 4; q++)
                acc[s][q] += av.x*xv[q].x + av.y*xv[q].y + av.z*xv[q].z + av.w*xv[q].w;
        }
    }
#pragma unroll
    for (int s = 0; s < 4; s++)
#pragma unroll
        for (int q = 0; q < 4; q++) {
            float v = acc[s][q];
#pragma unroll
            for (int o = 16; o > 0; o >>= 1) v += __shfl_xor_sync(~0u, v, o);
            if (l == 0) sred[q*32 + w*4 + s] = v;
        }
    __syncthreads();

    if (tid < 128) {
        int k = tid & 31, q = tid >> 5;
        float logit = sred[q*32 + k] * (1.f/25.6f);   // /C /TEMP
        float m = logit;
#pragma unroll
        for (int o = 16; o > 0; o >>= 1) m = fmaxf(m, __shfl_xor_sync(~0u, m, o));
        float p = expf(logit - m);
        float sum = p;
#pragma unroll
        for (int o = 16; o > 0; o >>= 1) sum += __shfl_xor_sync(~0u, sum, o);
        float h = p / sum;
        int gh = g / GW, gw = g % GW, qr = q >> 1, qc = q & 1;
        int lpos = (gh*2 + qr)*80 + gw*2 + qc;
        OUT[(long)lpos*K4 + k] = h;
    }
}

// ---------------- K5: mutual gating (dense scatter reduced to 8-way i10/i01 search) --
__global__ void k_gate01(float* __restrict__ out) {
    int idx = blockIdx.x*blockDim.x + threadIdx.x;    // (n, l0, k)
    if (idx >= NB*L*K4) return;
    int n  = idx / (L*K4);
    int l0 = (idx >> 5) % L;
    int j  = g_ind0[idx];
    int r0 = l0/80, c0 = l0%80;
    int e  = ((r0 & 1) << 1) | (c0 & 1);
    int gl = (r0 >> 1)*GW + (c0 >> 1);
    int gj = ((j/80) >> 1)*GW + ((j%80) >> 1);
    const int* i10p = g_i10 + (n*G + gj)*TOPK;
    float f = 0.f;
#pragma unroll
    for (int t = 0; t < TOPK; t++)
        if (i10p[t] == gl) { f = g_h10p[((long)n*L + j)*K4 + t*4 + e]; break; }
    out[idx] = g_h01p[idx] * f;
}

__global__ void k_gate10(float* __restrict__ out) {
    int idx = blockIdx.x*blockDim.x + threadIdx.x;    // (n, k, l1), l1 innermost
    if (idx >= NB*L*K4) return;
    int l1 = idx % L;
    int k  = (idx / L) % K4;
    int n  = idx / (L*K4);
    int l0 = g_ind1[((long)n*L + l1)*K4 + k];
    int r1 = l1/80, c1 = l1%80;
    int e  = ((r1 & 1) << 1) | (c1 & 1);
    int gl1 = (r1 >> 1)*GW + (c1 >> 1);
    int gl0 = ((l0/80) >> 1)*GW + ((l0%80) >> 1);
    const int* i01p = g_i01 + (n*G + gl0)*TOPK;
    float f = 0.f;
#pragma unroll
    for (int t = 0; t < TOPK; t++)
        if (i01p[t] == gl1) { f = g_h01p[((long)n*L + l0)*K4 + t*4 + e]; break; }
    out[idx] = g_h10p[((long)n*L + l1)*K4 + k] * f;
}

// ---------------- K6: coarse matching ----------------
__global__ void k_matchA(const float* __restrict__ h01) {
    int idx = blockIdx.x*blockDim.x + threadIdx.x;
    if (idx >= NB*L) return;
    int l0 = idx % L;
    const float* row = h01 + (long)idx*K4;
    float best = -1.f; int bk = 0;
#pragma unroll
    for (int k = 0; k < K4; k++) { float v = row[k]; if (v > best) { best = v; bk = k; } }
    g_score[idx] = best;
    int jb = g_ind0[(long)idx*K4 + bk];
    int r = l0/80, c = l0%80;
    if (r < 2 || r >= 78 || c < 2 || c >= 78) jb = 0;
    g_jb[idx] = jb;
}

__global__ void k_matchB(const float* __restrict__ h10) {
    int idx = blockIdx.x*blockDim.x + threadIdx.x;
    if (idx >= NB*L) return;
    int n = idx / L, l1 = idx % L;
    float best = -1.f; int bk = 0;
#pragma unroll
    for (int k = 0; k < K4; k++) {
        float v = h10[((long)n*K4 + k)*L + l1];
        if (v > best) { best = v; bk = k; }
    }
    int ib = g_ind1[((long)n*L + l1)*K4 + bk];
    int r = l1/80, c = l1%80;
    if (r < 2 || r >= 78 || c < 2 || c >= 78) ib = 0;
    g_ib[idx] = ib;
}

__global__ void k_matchC(float* __restrict__ osc, float* __restrict__ ojb,
                         float* __restrict__ omk) {
    int idx = blockIdx.x*blockDim.x + threadIdx.x;
    if (idx >= NB*L) return;
    int n = idx / L, l0 = idx % L;
    int jb = g_jb[idx];
    int biproj = g_ib[n*L + jb];
    float sc = g_score[idx];
    bool m = (biproj == l0) && (l0 != 0) && (sc > 0.2f);
    omk[idx] = m ? 1.f : 0.f;
    osc[idx] = m ? sc : 0.f;
    ojb[idx] = (float)jb;
}

// ---------------- K7: unpatchify via padded SMEM tile (both sides coalesced) --------
__global__ void k_unpatch(const float* __restrict__ x0, const float* __restrict__ x1,
                          float* __restrict__ out) {
    __shared__ float s[160*17];
    int c0 = blockIdx.x * 16;
    int gh = blockIdx.y;
    int which = blockIdx.z >> 1, n = blockIdx.z & 1;
    const float* X = (which == 0 ? x0 : x1) + (long)(n*G + gh*GW)*4*CH;
    float* O = out + (which == 0 ? OFF_X0 : OFF_X1);
    for (int idx = threadIdx.x; idx < 2560; idx += 256) {
        int gq = idx >> 4, cc = idx & 15;        // gq = g'*4 + q
        s[gq*17 + cc] = X[(long)gq*CH + c0 + cc];
    }
    __syncthreads();
    for (int idx = threadIdx.x; idx < 2560; idx += 256) {
        int w  = idx % 80;
        int t2 = idx / 80;
        int qr = t2 & 1, cc = t2 >> 1;
        int gp = w >> 1, qc = w & 1;
        float v = s[(gp*4 + qr*2 + qc)*17 + cc];
        O[(((long)(n*CH + c0 + cc))*80 + gh*2 + qr)*80 + w] = v;
    }
}

// ---------------- launch ----------------
extern "C" void kernel_launch(void* const* d_in, const int* in_sizes, int n_in,
                              void* d_out, int out_size) {
    const float* x0  = (const float*)d_in[0];
    const float* x1  = (const float*)d_in[1];
    const float* a01 = (const float*)d_in[2];
    const float* a10 = (const float*)d_in[3];
    const float* p0  = (const float*)d_in[4];
    const float* p1  = (const float*)d_in[5];
    float* out = (float*)d_out;

    k_gemm <<<dim3(13,25,2), 256>>>(p0, p1);
    k_tr   <<<dim3(50,50,2), dim3(32,8)>>>();
    k_topk <<<dim3(200,2,2), 256>>>();
    k_ind  <<<(NB*L*K4 + 255)/256, 256>>>();
    k_heat <<<dim3(G,2,2),   256>>>(x0, x1, a01, a10);
    k_gate01<<<(NB*L*K4 + 255)/256, 256>>>(out + OFF_H01);
    k_gate10<<<(NB*L*K4 + 255)/256, 256>>>(out + OFF_H10);
    k_matchA<<<(NB*L + 255)/256, 256>>>(out + OFF_H01);
    k_matchB<<<(NB*L + 255)/256, 256>>>(out + OFF_H10);
    k_matchC<<<(NB*L + 255)/256, 256>>>(out + OFF_SC, out + OFF_JB, out + OFF_MK);
    k_unpatch<<<dim3(16,40,4), 256>>>(x0, x1, out);
}

// round 3
// speedup vs baseline: 1.3382x; 1.0083x over previous
#include <cuda_runtime.h>
#include <math.h>

#define NB 2
#define CH 256
#define G 1600
#define GW 40
#define L 6400
#define TOPK 8
#define K4 32

#define OFF_H01 0
#define OFF_H10 (NB*L*K4)              /* 409600 */
#define OFF_SC  (OFF_H10 + NB*L*K4)    /* 819200 */
#define OFF_JB  (OFF_SC + NB*L)        /* 832000 */
#define OFF_MK  (OFF_JB + NB*L)        /* 844800 */
#define OFF_X0  (OFF_MK + NB*L)        /* 857600 */
#define OFF_X1  (OFF_X0 + NB*CH*L)     /* 4134400 */

// Block-role layout for fat kernel P1
#define NGEMM 650                       /* 13 x 25 x 2 */
#define NHEAT 6400                      /* 1600 x 2 x 2 */
#define NUNP  2560                      /* 16 x 40 x 4 */

// ---------------- scratch ----------------
__device__ float g_sim [NB*G*G];         // 20.5 MB
__device__ int   g_i01[NB*G*TOPK];
__device__ int   g_i10[NB*G*TOPK];
__device__ float g_h01p[NB*L*K4];        // ungated h01, (n, l0, k)
__device__ float g_h10p[NB*L*K4];        // ungated h10, (n, l1, k)
__device__ float g_score[NB*L];
__device__ int   g_jb[NB*L];
__device__ int   g_ib[NB*L];

// fine index from coarse index + corner e (ey, ex)
__device__ __forceinline__ int fine_idx(int coarse, int ey, int ex) {
    return ((coarse/GW)*2 + ey)*80 + (coarse%GW)*2 + ex;
}

// =====================================================================
// P1: fat kernel — gemm (blocks [0,650)), heat [650,7050), unpatch [7050,9610)
// =====================================================================
__global__ __launch_bounds__(256)
void k_p1(const float* __restrict__ x0, const float* __restrict__ x1,
          const float* __restrict__ a01, const float* __restrict__ a10,
          const float* __restrict__ p0, const float* __restrict__ p1,
          float* __restrict__ out) {
    __shared__ float smem_u[3072];      // 12 KB union
    const int b = blockIdx.x;
    const int tid = threadIdx.x;

    if (b < NGEMM) {
        // ---------- GEMM role: sim = p0^T p1, 64x128 tile ----------
        int bb = b;
        int n  = bb / 325; bb %= 325;
        int by = bb / 13;               // 25 row-tiles
        int bx = bb % 13;               // 13 col-tiles
        const float* A = p0 + (long)n*CH*G;
        const float* B = p1 + (long)n*CH*G;
        float* S = g_sim + (long)n*G*G;
        float (*As)[64]  = (float(*)[64]) smem_u;          // 16x64
        float (*Bs)[128] = (float(*)[128])(smem_u + 1024); // 16x128
        const int tx = tid & 15, ty = tid >> 4;
        const int i0 = by * 64, j0 = bx * 128;
        float acc[4][8];
#pragma unroll
        for (int a = 0; a < 4; a++)
#pragma unroll
            for (int c = 0; c < 8; c++) acc[a][c] = 0.f;

        for (int k0 = 0; k0 < CH; k0 += 16) {
            {
                int kk = tid >> 4, ii = (tid & 15) << 2;
                *(float4*)&As[kk][ii] = *(const float4*)(A + (long)(k0 + kk)*G + i0 + ii);
            }
#pragma unroll
            for (int r = 0; r < 2; r++) {
                int idx = tid + r*256;
                int kk = idx >> 5, jj = (idx & 31) << 2;
                int gj = j0 + jj;
                float4 v = make_float4(0.f,0.f,0.f,0.f);
                if (gj < G) v = *(const float4*)(B + (long)(k0 + kk)*G + gj);
                *(float4*)&Bs[kk][jj] = v;
            }
            __syncthreads();
#pragma unroll
            for (int kk = 0; kk < 16; kk++) {
                float4 ra  = *(const float4*)&As[kk][ty*4];
                float4 rb0 = *(const float4*)&Bs[kk][tx*8];
                float4 rb1 = *(const float4*)&Bs[kk][tx*8 + 4];
                float ar[4] = {ra.x, ra.y, ra.z, ra.w};
                float br[8] = {rb0.x, rb0.y, rb0.z, rb0.w, rb1.x, rb1.y, rb1.z, rb1.w};
#pragma unroll
                for (int a = 0; a < 4; a++)
#pragma unroll
                    for (int c = 0; c < 8; c++) acc[a][c] += ar[a]*br[c];
            }
            __syncthreads();
        }
#pragma unroll
        for (int a = 0; a < 4; a++) {
            int i = i0 + ty*4 + a;
#pragma unroll
            for (int b4 = 0; b4 < 2; b4++) {
                int j = j0 + tx*8 + b4*4;
                if (j < G)
                    *(float4*)(S + (long)i*G + j) =
                        make_float4(acc[a][b4*4], acc[a][b4*4+1],
                                    acc[a][b4*4+2], acc[a][b4*4+3]);
            }
        }
    } else if (b < NGEMM + NHEAT) {
        // ---------- HEAT role ----------
        int r = b - NGEMM;
        int g = r % G;
        int n = (r / G) & 1;
        int dir = r / (2*G);
        const float* X = (dir == 0 ? x0  : x1 ) + (long)(n*G + g)*4*CH;
        const float* A = (dir == 0 ? a01 : a10) + (long)(n*G + g)*K4*CH;
        float* OUT = (dir == 0 ? g_h01p : g_h10p) + (long)n*L*K4;
        float* xs = smem_u;                 // 1024 floats
        float* sred = smem_u + 1024;        // 128 floats

        ((float4*)xs)[tid] = ((const float4*)X)[tid];
        __syncthreads();

        int w = tid >> 5, l = tid & 31;
        const float4* A4 = (const float4*)A + (long)(w*4)*64;
        float acc[4][4];
#pragma unroll
        for (int s = 0; s < 4; s++)
#pragma unroll
            for (int q = 0; q < 4; q++) acc[s][q] = 0.f;
#pragma unroll
        for (int it = 0; it < 2; it++) {
            float4 xv[4];
#pragma unroll
            for (int q = 0; q < 4; q++) xv[q] = ((const float4*)xs)[q*64 + it*32 + l];
#pragma unroll
            for (int s = 0; s < 4; s++) {
                float4 av = A4[s*64 + it*32 + l];
#pragma unroll
                for (int q = 0; q < 4; q++)
                    acc[s][q] += av.x*xv[q].x + av.y*xv[q].y + av.z*xv[q].z + av.w*xv[q].w;
            }
        }
#pragma unroll
        for (int s = 0; s < 4; s++)
#pragma unroll
            for (int q = 0; q < 4; q++) {
                float v = acc[s][q];
#pragma unroll
                for (int o = 16; o > 0; o >>= 1) v += __shfl_xor_sync(~0u, v, o);
                if (l == 0) sred[q*32 + w*4 + s] = v;
            }
        __syncthreads();

        if (tid < 128) {
            int k = tid & 31, q = tid >> 5;
            float logit = sred[q*32 + k] * (1.f/25.6f);
            float m = logit;
#pragma unroll
            for (int o = 16; o > 0; o >>= 1) m = fmaxf(m, __shfl_xor_sync(~0u, m, o));
            float p = expf(logit - m);
            float sum = p;
#pragma unroll
            for (int o = 16; o > 0; o >>= 1) sum += __shfl_xor_sync(~0u, sum, o);
            float h = p / sum;
            int gh = g / GW, gw = g % GW, qr = q >> 1, qc = q & 1;
            int lpos = (gh*2 + qr)*80 + gw*2 + qc;
            OUT[(long)lpos*K4 + k] = h;
        }
    } else {
        // ---------- UNPATCH role ----------
        int r2 = b - NGEMM - NHEAT;
        int c0 = (r2 % 16) * 16;
        int gh = (r2 / 16) % 40;
        int bz = r2 / 640;
        int which = bz >> 1, n = bz & 1;
        const float* X = (which == 0 ? x0 : x1) + (long)(n*G + gh*GW)*4*CH;
        float* O = out + (which == 0 ? OFF_X0 : OFF_X1);
        float* s = smem_u;                  // 160*17 = 2720 floats
        for (int idx = tid; idx < 2560; idx += 256) {
            int gq = idx >> 4, cc = idx & 15;
            s[gq*17 + cc] = X[(long)gq*CH + c0 + cc];
        }
        __syncthreads();
        for (int idx = tid; idx < 2560; idx += 256) {
            int w  = idx % 80;
            int t2 = idx / 80;
            int qr = t2 & 1, cc = t2 >> 1;
            int gp = w >> 1, qc = w & 1;
            float v = s[(gp*4 + qr*2 + qc)*17 + cc];
            O[(((long)(n*CH + c0 + cc))*80 + gh*2 + qr)*80 + w] = v;
        }
    }
}

// =====================================================================
// P2: top-8 — rows (warp-per-row, blocks [0,400)) + cols (streaming, [400,500))
// jax.lax.top_k semantics: descending value, ties -> smaller index first.
// =====================================================================
__global__ __launch_bounds__(256)
void k_topk() {
    const int b = blockIdx.x;
    if (b < 400) {
        int w = threadIdx.x >> 5, l = threadIdx.x & 31;
        int n = b / 200;
        int row = (b % 200) * 8 + w;
        const float* Srow = g_sim + (long)n*G*G + (long)row*G;
        float v[50];
#pragma unroll
        for (int j = 0; j < 50; j++) v[j] = Srow[j*32 + l];
        int* outp = g_i01 + (n*G + row)*TOPK;
#pragma unroll
        for (int r = 0; r < TOPK; r++) {
            float best = -INFINITY; int bi = 1 << 30;
#pragma unroll
            for (int j = 0; j < 50; j++) {
                float val = v[j];
                int i = j*32 + l;
                if (val > best || (val == best && i < bi)) { best = val; bi = i; }
            }
#pragma unroll
            for (int o = 16; o > 0; o >>= 1) {
                float ov = __shfl_xor_sync(~0u, best, o);
                int   oi = __shfl_xor_sync(~0u, bi, o);
                if (ov > best || (ov == best && oi < bi)) { best = ov; bi = oi; }
            }
            if (l == 0) outp[r] = bi;
            if ((bi & 31) == l) {
                int jw = bi >> 5;
#pragma unroll
                for (int j = 0; j < 50; j++) if (j == jw) v[j] = -INFINITY;
            }
        }
    } else {
        // column top-8 via streaming sorted insertion (no transpose needed)
        __shared__ float sv[2048];
        __shared__ int   si[2048];
        int bb = b - 400;
        int n = bb / 50;
        int c0 = (bb % 50) * 32;
        int c = threadIdx.x & 31, r = threadIdx.x >> 5;   // 8 row-groups x 32 cols
        int col = c0 + c;
        const float* S = g_sim + (long)n*G*G;
        float tv[8]; int ti[8];
#pragma unroll
        for (int j = 0; j < 8; j++) { tv[j] = -INFINITY; ti[j] = 1 << 30; }
#pragma unroll 4
        for (int i = r; i < G; i += 8) {
            float v = S[(long)i*G + col];
            if (v > tv[7]) {
                tv[7] = v; ti[7] = i;
#pragma unroll
                for (int j = 6; j >= 0; j--) {
                    if (tv[j+1] > tv[j]) {
                        float fv = tv[j]; tv[j] = tv[j+1]; tv[j+1] = fv;
                        int   fi = ti[j]; ti[j] = ti[j+1]; ti[j+1] = fi;
                    }
                }
            }
        }
#pragma unroll
        for (int j = 0; j < 8; j++) {
            sv[(r*32 + c)*8 + j] = tv[j];
            si[(r*32 + c)*8 + j] = ti[j];
        }
        __syncthreads();
        if (threadIdx.x < 32) {
            int cc = threadIdx.x;
            int* outp = g_i10 + (n*G + c0 + cc)*TOPK;
#pragma unroll
            for (int rr = 0; rr < TOPK; rr++) {
                float best = -INFINITY; int bi = 1 << 30, bp = -1;
                for (int p = 0; p < 64; p++) {
                    int off = ((p >> 3)*32 + cc)*8 + (p & 7);
                    float v = sv[off]; int i = si[off];
                    if (v > best || (v == best && i < bi)) { best = v; bi = i; bp = off; }
                }
                outp[rr] = bi;
                sv[bp] = -INFINITY;
            }
        }
    }
}

// =====================================================================
// P3: gates (+matchA fused into gate01). blocks [0,1600): gate01 warp-per-l0;
//     blocks [1600,3200): gate10 thread-per-(n,k,l1).
// =====================================================================
__global__ __launch_bounds__(256)
void k_gate(float* __restrict__ out) {
    const int b = blockIdx.x;
    if (b < 1600) {
        // gate01 + matchA: warp per (n, l0), lane = k
        int w = threadIdx.x >> 5, k = threadIdx.x & 31;
        int widx = b*8 + w;                 // over NB*L
        int n = widx / L, l0 = widx % L;
        int r0 = l0/80, c0 = l0%80;
        int e  = ((r0 & 1) << 1) | (c0 & 1);
        int gl = (r0 >> 1)*GW + (c0 >> 1);
        int t = k >> 2, ke = k & 3;
        int c01 = g_i01[(n*G + gl)*TOPK + t];
        int j = fine_idx(c01, ke >> 1, ke & 1);
        int gj = ((j/80) >> 1)*GW + ((j%80) >> 1);
        const int* i10p = g_i10 + (n*G + gj)*TOPK;
        float f = 0.f;
#pragma unroll
        for (int t2 = 0; t2 < TOPK; t2++)
            if (i10p[t2] == gl) { f = g_h10p[((long)n*L + j)*K4 + t2*4 + e]; break; }
        float val = g_h01p[(long)widx*K4 + k] * f;
        out[(long)widx*K4 + k] = val;
        // warp argmax (first max -> smallest k on ties)
        float best = val; int bk = k;
#pragma unroll
        for (int o = 16; o > 0; o >>= 1) {
            float ov = __shfl_xor_sync(~0u, best, o);
            int   ok = __shfl_xor_sync(~0u, bk, o);
            if (ov > best || (ov == best && ok < bk)) { best = ov; bk = ok; }
        }
        int jb = __shfl_sync(~0u, j, bk);
        if (k == 0) {
            if (r0 < 2 || r0 >= 78 || c0 < 2 || c0 >= 78) jb = 0;
            g_score[widx] = best;
            g_jb[widx] = jb;
        }
    } else {
        // gate10: idx over (n, k, l1), l1 innermost (coalesced writes)
        int idx = (b - 1600)*256 + threadIdx.x;
        int l1 = idx % L;
        int k  = (idx / L) % K4;
        int n  = idx / (L*K4);
        int r1 = l1/80, c1 = l1%80;
        int e  = ((r1 & 1) << 1) | (c1 & 1);
        int gl1 = (r1 >> 1)*GW + (c1 >> 1);
        int t = k >> 2, ke = k & 3;
        int c10 = g_i10[(n*G + gl1)*TOPK + t];
        int l0 = fine_idx(c10, ke >> 1, ke & 1);
        int gl0 = ((l0/80) >> 1)*GW + ((l0%80) >> 1);
        const int* i01p = g_i01 + (n*G + gl0)*TOPK;
        float f = 0.f;
#pragma unroll
        for (int t2 = 0; t2 < TOPK; t2++)
            if (i01p[t2] == gl1) { f = g_h01p[((long)n*L + l0)*K4 + t2*4 + e]; break; }
        out[OFF_H10 + idx] = g_h10p[((long)n*L + l1)*K4 + k] * f;
    }
}

// ---------------- matchB ----------------
__global__ void k_matchB(const float* __restrict__ h10) {
    int idx = blockIdx.x*blockDim.x + threadIdx.x;
    if (idx >= NB*L) return;
    int n = idx / L, l1 = idx % L;
    float best = -1.f; int bk = 0;
#pragma unroll
    for (int k = 0; k < K4; k++) {
        float v = h10[((long)n*K4 + k)*L + l1];
        if (v > best) { best = v; bk = k; }
    }
    int r1 = l1/80, c1 = l1%80;
    int gl1 = (r1 >> 1)*GW + (c1 >> 1);
    int c10 = g_i10[(n*G + gl1)*TOPK + (bk >> 2)];
    int ib = fine_idx(c10, (bk & 3) >> 1, bk & 1);
    if (r1 < 2 || r1 >= 78 || c1 < 2 || c1 >= 78) ib = 0;
    g_ib[idx] = ib;
}

// ---------------- matchC ----------------
__global__ void k_matchC(float* __restrict__ osc, float* __restrict__ ojb,
                         float* __restrict__ omk) {
    int idx = blockIdx.x*blockDim.x + threadIdx.x;
    if (idx >= NB*L) return;
    int n = idx / L, l0 = idx % L;
    int jb = g_jb[idx];
    int biproj = g_ib[n*L + jb];
    float sc = g_score[idx];
    bool m = (biproj == l0) && (l0 != 0) && (sc > 0.2f);
    omk[idx] = m ? 1.f : 0.f;
    osc[idx] = m ? sc : 0.f;
    ojb[idx] = (float)jb;
}

// ---------------- launch ----------------
extern "C" void kernel_launch(void* const* d_in, const int* in_sizes, int n_in,
                              void* d_out, int out_size) {
    const float* x0  = (const float*)d_in[0];
    const float* x1  = (const float*)d_in[1];
    const float* a01 = (const float*)d_in[2];
    const float* a10 = (const float*)d_in[3];
    const float* p0  = (const float*)d_in[4];
    const float* p1  = (const float*)d_in[5];
    float* out = (float*)d_out;

    k_p1   <<<NGEMM + NHEAT + NUNP, 256>>>(x0, x1, a01, a10, p0, p1, out);
    k_topk <<<500, 256>>>();
    k_gate <<<3200, 256>>>(out);
    k_matchB<<<(NB*L + 255)/256, 256>>>(out + OFF_H10);
    k_matchC<<<(NB*L + 255)/256, 256>>>(out + OFF_SC, out + OFF_JB, out + OFF_MK);
}

// round 4
// speedup vs baseline: 1.5441x; 1.1539x over previous
#include <cuda_runtime.h>
#include <math.h>

#define NB 2
#define CH 256
#define G 1600
#define GW 40
#define L 6400
#define TOPK 8
#define K4 32

#define OFF_H01 0
#define OFF_H10 (NB*L*K4)              /* 409600 */
#define OFF_SC  (OFF_H10 + NB*L*K4)    /* 819200 */
#define OFF_JB  (OFF_SC + NB*L)        /* 832000 */
#define OFF_MK  (OFF_JB + NB*L)        /* 844800 */
#define OFF_X0  (OFF_MK + NB*L)        /* 857600 */
#define OFF_X1  (OFF_X0 + NB*CH*L)     /* 4134400 */

// Block-role layout for fat kernel P1
#define NGEMM 650                       /* 13 x 25 x 2 */
#define NHEAT 6400                      /* 1600 x 2 x 2 */
#define NUNP  2560                      /* 16 x 40 x 4 */

// ---------------- scratch ----------------
__device__ float g_sim [NB*G*G];         // 20.5 MB
__device__ int   g_i01[NB*G*TOPK];
__device__ int   g_i10[NB*G*TOPK];
__device__ float g_h01p[NB*L*K4];        // ungated h01, (n, l0, k)
__device__ float g_h10p[NB*L*K4];        // ungated h10, (n, l1, k)
__device__ float g_score[NB*L];
__device__ int   g_jb[NB*L];
__device__ int   g_ib[NB*L];

// fine index from coarse index + corner e (ey, ex)
__device__ __forceinline__ int fine_idx(int coarse, int ey, int ex) {
    return ((coarse/GW)*2 + ey)*80 + (coarse%GW)*2 + ex;
}

// =====================================================================
// P1: fat kernel — gemm (blocks [0,650)), heat [650,7050), unpatch [7050,9610)
// =====================================================================
__global__ __launch_bounds__(256)
void k_p1(const float* __restrict__ x0, const float* __restrict__ x1,
          const float* __restrict__ a01, const float* __restrict__ a10,
          const float* __restrict__ p0, const float* __restrict__ p1,
          float* __restrict__ out) {
    __shared__ float smem_u[3072];      // 12 KB union
    const int b = blockIdx.x;
    const int tid = threadIdx.x;

    if (b < NGEMM) {
        // ---------- GEMM role: sim = p0^T p1, 64x128 tile, conflict-free ----------
        int bb = b;
        int n  = bb / 325; bb %= 325;
        int by = bb / 13;               // 25 row-tiles (exact)
        int bx = bb % 13;               // 13 col-tiles (bounded)
        const float* A = p0 + (long)n*CH*G;
        const float* B = p1 + (long)n*CH*G;
        float* S = g_sim + (long)n*G*G;
        float (*As)[64]  = (float(*)[64]) smem_u;          // 16x64
        float (*Bs)[128] = (float(*)[128])(smem_u + 1024); // 16x128
        const int tx = tid & 15, ty = tid >> 4;
        const int i0 = by * 64, j0 = bx * 128;
        float acc[4][8];
#pragma unroll
        for (int a = 0; a < 4; a++)
#pragma unroll
            for (int c = 0; c < 8; c++) acc[a][c] = 0.f;

        for (int k0 = 0; k0 < CH; k0 += 16) {
            {
                int kk = tid >> 4, ii = (tid & 15) << 2;
                *(float4*)&As[kk][ii] = *(const float4*)(A + (long)(k0 + kk)*G + i0 + ii);
            }
#pragma unroll
            for (int r = 0; r < 2; r++) {
                int idx = tid + r*256;
                int kk = idx >> 5, jj = (idx & 31) << 2;
                int gj = j0 + jj;
                float4 v = make_float4(0.f,0.f,0.f,0.f);
                if (gj < G) v = *(const float4*)(B + (long)(k0 + kk)*G + gj);
                *(float4*)&Bs[kk][jj] = v;
            }
            __syncthreads();
#pragma unroll
            for (int kk = 0; kk < 16; kk++) {
                // A: 2 distinct addrs per warp -> broadcast.
                // B: 16-byte lane stride -> all 32 banks, conflict-free.
                float4 ra  = *(const float4*)&As[kk][ty*4];
                float4 rb0 = *(const float4*)&Bs[kk][tx*4];
                float4 rb1 = *(const float4*)&Bs[kk][64 + tx*4];
                float ar[4] = {ra.x, ra.y, ra.z, ra.w};
                float br[8] = {rb0.x, rb0.y, rb0.z, rb0.w, rb1.x, rb1.y, rb1.z, rb1.w};
#pragma unroll
                for (int a = 0; a < 4; a++)
#pragma unroll
                    for (int c = 0; c < 8; c++) acc[a][c] += ar[a]*br[c];
            }
            __syncthreads();
        }
        // columns: j0 + tx*4 (acc[.][0..3]) and j0 + 64 + tx*4 (acc[.][4..7])
#pragma unroll
        for (int a = 0; a < 4; a++) {
            int i = i0 + ty*4 + a;
            int j = j0 + tx*4;
            if (j < G)
                *(float4*)(S + (long)i*G + j) =
                    make_float4(acc[a][0], acc[a][1], acc[a][2], acc[a][3]);
            j += 64;
            if (j < G)
                *(float4*)(S + (long)i*G + j) =
                    make_float4(acc[a][4], acc[a][5], acc[a][6], acc[a][7]);
        }
    } else if (b < NGEMM + NHEAT) {
        // ---------- HEAT role ----------
        int r = b - NGEMM;
        int g = r % G;
        int n = (r / G) & 1;
        int dir = r / (2*G);
        const float* X = (dir == 0 ? x0  : x1 ) + (long)(n*G + g)*4*CH;
        const float* A = (dir == 0 ? a01 : a10) + (long)(n*G + g)*K4*CH;
        float* OUT = (dir == 0 ? g_h01p : g_h10p) + (long)n*L*K4;
        float* xs = smem_u;                 // 1024 floats
        float* sred = smem_u + 1024;        // 128 floats

        ((float4*)xs)[tid] = ((const float4*)X)[tid];
        __syncthreads();

        int w = tid >> 5, l = tid & 31;
        const float4* A4 = (const float4*)A + (long)(w*4)*64;
        float acc[4][4];
#pragma unroll
        for (int s = 0; s < 4; s++)
#pragma unroll
            for (int q = 0; q < 4; q++) acc[s][q] = 0.f;
#pragma unroll
        for (int it = 0; it < 2; it++) {
            float4 xv[4];
#pragma unroll
            for (int q = 0; q < 4; q++) xv[q] = ((const float4*)xs)[q*64 + it*32 + l];
#pragma unroll
            for (int s = 0; s < 4; s++) {
                float4 av = A4[s*64 + it*32 + l];
#pragma unroll
                for (int q = 0; q < 4; q++)
                    acc[s][q] += av.x*xv[q].x + av.y*xv[q].y + av.z*xv[q].z + av.w*xv[q].w;
            }
        }
#pragma unroll
        for (int s = 0; s < 4; s++)
#pragma unroll
            for (int q = 0; q < 4; q++) {
                float v = acc[s][q];
#pragma unroll
                for (int o = 16; o > 0; o >>= 1) v += __shfl_xor_sync(~0u, v, o);
                if (l == 0) sred[q*32 + w*4 + s] = v;
            }
        __syncthreads();

        if (tid < 128) {
            int k = tid & 31, q = tid >> 5;
            float logit = sred[q*32 + k] * (1.f/25.6f);
            float m = logit;
#pragma unroll
            for (int o = 16; o > 0; o >>= 1) m = fmaxf(m, __shfl_xor_sync(~0u, m, o));
            float p = expf(logit - m);
            float sum = p;
#pragma unroll
            for (int o = 16; o > 0; o >>= 1) sum += __shfl_xor_sync(~0u, sum, o);
            float h = p / sum;
            int gh = g / GW, gw = g % GW, qr = q >> 1, qc = q & 1;
            int lpos = (gh*2 + qr)*80 + gw*2 + qc;
            OUT[(long)lpos*K4 + k] = h;
        }
    } else {
        // ---------- UNPATCH role ----------
        int r2 = b - NGEMM - NHEAT;
        int c0 = (r2 % 16) * 16;
        int gh = (r2 / 16) % 40;
        int bz = r2 / 640;
        int which = bz >> 1, n = bz & 1;
        const float* X = (which == 0 ? x0 : x1) + (long)(n*G + gh*GW)*4*CH;
        float* O = out + (which == 0 ? OFF_X0 : OFF_X1);
        float* s = smem_u;                  // 160*17 = 2720 floats
        for (int idx = tid; idx < 2560; idx += 256) {
            int gq = idx >> 4, cc = idx & 15;
            s[gq*17 + cc] = X[(long)gq*CH + c0 + cc];
        }
        __syncthreads();
        for (int idx = tid; idx < 2560; idx += 256) {
            int w  = idx % 80;
            int t2 = idx / 80;
            int qr = t2 & 1, cc = t2 >> 1;
            int gp = w >> 1, qc = w & 1;
            float v = s[(gp*4 + qr*2 + qc)*17 + cc];
            O[(((long)(n*CH + c0 + cc))*80 + gh*2 + qr)*80 + w] = v;
        }
    }
}

// =====================================================================
// P2: top-8 — rows (warp-per-row, blocks [0,400)) + cols (streaming, [400,500))
// jax.lax.top_k semantics: descending value, ties -> smaller index first.
// =====================================================================
__global__ __launch_bounds__(256)
void k_topk() {
    const int b = blockIdx.x;
    if (b < 400) {
        int w = threadIdx.x >> 5, l = threadIdx.x & 31;
        int n = b / 200;
        int row = (b % 200) * 8 + w;
        const float* Srow = g_sim + (long)n*G*G + (long)row*G;
        float v[50];
#pragma unroll
        for (int j = 0; j < 50; j++) v[j] = Srow[j*32 + l];
        int* outp = g_i01 + (n*G + row)*TOPK;
#pragma unroll
        for (int r = 0; r < TOPK; r++) {
            float best = -INFINITY; int bi = 1 << 30;
#pragma unroll
            for (int j = 0; j < 50; j++) {
                float val = v[j];
                int i = j*32 + l;
                if (val > best || (val == best && i < bi)) { best = val; bi = i; }
            }
#pragma unroll
            for (int o = 16; o > 0; o >>= 1) {
                float ov = __shfl_xor_sync(~0u, best, o);
                int   oi = __shfl_xor_sync(~0u, bi, o);
                if (ov > best || (ov == best && oi < bi)) { best = ov; bi = oi; }
            }
            if (l == 0) outp[r] = bi;
            if ((bi & 31) == l) {
                int jw = bi >> 5;
#pragma unroll
                for (int j = 0; j < 50; j++) if (j == jw) v[j] = -INFINITY;
            }
        }
    } else {
        // column top-8 via streaming sorted insertion (no transpose needed)
        __shared__ float sv[2048];
        __shared__ int   si[2048];
        int bb = b - 400;
        int n = bb / 50;
        int c0 = (bb % 50) * 32;
        int c = threadIdx.x & 31, r = threadIdx.x >> 5;   // 8 row-groups x 32 cols
        int col = c0 + c;
        const float* S = g_sim + (long)n*G*G;
        float tv[8]; int ti[8];
#pragma unroll
        for (int j = 0; j < 8; j++) { tv[j] = -INFINITY; ti[j] = 1 << 30; }
#pragma unroll 4
        for (int i = r; i < G; i += 8) {
            float v = S[(long)i*G + col];
            if (v > tv[7]) {
                tv[7] = v; ti[7] = i;
#pragma unroll
                for (int j = 6; j >= 0; j--) {
                    if (tv[j+1] > tv[j]) {
                        float fv = tv[j]; tv[j] = tv[j+1]; tv[j+1] = fv;
                        int   fi = ti[j]; ti[j] = ti[j+1]; ti[j+1] = fi;
                    }
                }
            }
        }
#pragma unroll
        for (int j = 0; j < 8; j++) {
            sv[(r*32 + c)*8 + j] = tv[j];
            si[(r*32 + c)*8 + j] = ti[j];
        }
        __syncthreads();
        if (threadIdx.x < 32) {
            int cc = threadIdx.x;
            int* outp = g_i10 + (n*G + c0 + cc)*TOPK;
#pragma unroll
            for (int rr = 0; rr < TOPK; rr++) {
                float best = -INFINITY; int bi = 1 << 30, bp = -1;
                for (int p = 0; p < 64; p++) {
                    int off = ((p >> 3)*32 + cc)*8 + (p & 7);
                    float v = sv[off]; int i = si[off];
                    if (v > best || (v == best && i < bi)) { best = v; bi = i; bp = off; }
                }
                outp[rr] = bi;
                sv[bp] = -INFINITY;
            }
        }
    }
}

// =====================================================================
// P3: gates + matchA + matchB.
//   [0,1600):     gate01+matchA, warp per (n,l0), lane=k
//   [1600,3200):  gate10 elementwise, l1 innermost (coalesced k-major writes)
//   [3200,4800):  matchB, warp per (n,l1), lane=k, recomputes gate from h10p
// =====================================================================
__global__ __launch_bounds__(256)
void k_gate(float* __restrict__ out) {
    const int b = blockIdx.x;
    if (b < 1600) {
        int w = threadIdx.x >> 5, k = threadIdx.x & 31;
        int widx = b*8 + w;                 // over NB*L
        int n = widx / L, l0 = widx % L;
        int r0 = l0/80, c0 = l0%80;
        int e  = ((r0 & 1) << 1) | (c0 & 1);
        int gl = (r0 >> 1)*GW + (c0 >> 1);
        int t = k >> 2, ke = k & 3;
        int c01 = g_i01[(n*G + gl)*TOPK + t];
        int j = fine_idx(c01, ke >> 1, ke & 1);
        int gj = ((j/80) >> 1)*GW + ((j%80) >> 1);
        const int* i10p = g_i10 + (n*G + gj)*TOPK;
        float f = 0.f;
#pragma unroll
        for (int t2 = 0; t2 < TOPK; t2++)
            if (i10p[t2] == gl) { f = g_h10p[((long)n*L + j)*K4 + t2*4 + e]; break; }
        float val = g_h01p[(long)widx*K4 + k] * f;
        out[(long)widx*K4 + k] = val;
        float best = val; int bk = k;
#pragma unroll
        for (int o = 16; o > 0; o >>= 1) {
            float ov = __shfl_xor_sync(~0u, best, o);
            int   ok = __shfl_xor_sync(~0u, bk, o);
            if (ov > best || (ov == best && ok < bk)) { best = ov; bk = ok; }
        }
        int jb = __shfl_sync(~0u, j, bk);
        if (k == 0) {
            if (r0 < 2 || r0 >= 78 || c0 < 2 || c0 >= 78) jb = 0;
            g_score[widx] = best;
            g_jb[widx] = jb;
        }
    } else if (b < 3200) {
        int idx = (b - 1600)*256 + threadIdx.x;
        int l1 = idx % L;
        int k  = (idx / L) % K4;
        int n  = idx / (L*K4);
        int r1 = l1/80, c1 = l1%80;
        int e  = ((r1 & 1) << 1) | (c1 & 1);
        int gl1 = (r1 >> 1)*GW + (c1 >> 1);
        int t = k >> 2, ke = k & 3;
        int c10 = g_i10[(n*G + gl1)*TOPK + t];
        int l0 = fine_idx(c10, ke >> 1, ke & 1);
        int gl0 = ((l0/80) >> 1)*GW + ((l0%80) >> 1);
        const int* i01p = g_i01 + (n*G + gl0)*TOPK;
        float f = 0.f;
#pragma unroll
        for (int t2 = 0; t2 < TOPK; t2++)
            if (i01p[t2] == gl1) { f = g_h01p[((long)n*L + l0)*K4 + t2*4 + e]; break; }
        out[OFF_H10 + idx] = g_h10p[((long)n*L + l1)*K4 + k] * f;
    } else {
        // matchB role: warp per (n,l1); recompute gated value (reads contiguous h10p)
        int w = threadIdx.x >> 5, k = threadIdx.x & 31;
        int widx = (b - 3200)*8 + w;        // over NB*L
        int n = widx / L, l1 = widx % L;
        int r1 = l1/80, c1 = l1%80;
        int e  = ((r1 & 1) << 1) | (c1 & 1);
        int gl1 = (r1 >> 1)*GW + (c1 >> 1);
        int t = k >> 2, ke = k & 3;
        int c10 = g_i10[(n*G + gl1)*TOPK + t];
        int l0 = fine_idx(c10, ke >> 1, ke & 1);
        int gl0 = ((l0/80) >> 1)*GW + ((l0%80) >> 1);
        const int* i01p = g_i01 + (n*G + gl0)*TOPK;
        float f = 0.f;
#pragma unroll
        for (int t2 = 0; t2 < TOPK; t2++)
            if (i01p[t2] == gl1) { f = g_h01p[((long)n*L + l0)*K4 + t2*4 + e]; break; }
        float val = g_h10p[(long)widx*K4 + k] * f;
        // argmax over k, ties -> smallest k (matches first-occurrence argmax)
        float best = val; int bk = k;
#pragma unroll
        for (int o = 16; o > 0; o >>= 1) {
            float ov = __shfl_xor_sync(~0u, best, o);
            int   ok = __shfl_xor_sync(~0u, bk, o);
            if (ov > best || (ov == best && ok < bk)) { best = ov; bk = ok; }
        }
        int ib = __shfl_sync(~0u, l0, bk);
        if (k == 0) {
            if (r1 < 2 || r1 >= 78 || c1 < 2 || c1 >= 78) ib = 0;
            g_ib[widx] = ib;
        }
    }
}

// ---------------- matchC ----------------
__global__ void k_matchC(float* __restrict__ osc, float* __restrict__ ojb,
                         float* __restrict__ omk) {
    int idx = blockIdx.x*blockDim.x + threadIdx.x;
    if (idx >= NB*L) return;
    int n = idx / L, l0 = idx % L;
    int jb = g_jb[idx];
    int biproj = g_ib[n*L + jb];
    float sc = g_score[idx];
    bool m = (biproj == l0) && (l0 != 0) && (sc > 0.2f);
    omk[idx] = m ? 1.f : 0.f;
    osc[idx] = m ? sc : 0.f;
    ojb[idx] = (float)jb;
}

// ---------------- launch ----------------
extern "C" void kernel_launch(void* const* d_in, const int* in_sizes, int n_in,
                              void* d_out, int out_size) {
    const float* x0  = (const float*)d_in[0];
    const float* x1  = (const float*)d_in[1];
    const float* a01 = (const float*)d_in[2];
    const float* a10 = (const float*)d_in[3];
    const float* p0  = (const float*)d_in[4];
    const float* p1  = (const float*)d_in[5];
    float* out = (float*)d_out;

    k_p1   <<<NGEMM + NHEAT + NUNP, 256>>>(x0, x1, a01, a10, p0, p1, out);
    k_topk <<<500, 256>>>();
    k_gate <<<4800, 256>>>(out);
    k_matchC<<<(NB*L + 255)/256, 256>>>(out + OFF_SC, out + OFF_JB, out + OFF_MK);
}